// round 16
// baseline (speedup 1.0000x reference)
#include <cuda_runtime.h>
#include <cuda_bf16.h>
#include <cstdint>

#define Bb 8
#define Nn 2048
#define Kk 256
#define Ff 128
#define NCH 32
#define CSZ 64
#define GRID 128
#define NTHR 256

// -------- scratch (device globals) --------
__device__ __align__(16) float g_Wh[Bb*Nn*Ff];
__device__ float g_u [Bb*Nn];
__device__ float g_v [Bb*Nn];
__device__ float g_wa_i[Kk];
__device__ float g_wa_j[Kk];
__device__ __align__(16) __nv_bfloat16 g_h_hi[Bb*Nn*Kk];
__device__ __align__(16) __nv_bfloat16 g_h_lo[Bb*Nn*Kk];
__device__ __align__(16) __nv_bfloat16 g_W_hi[Kk*Ff];
__device__ __align__(16) __nv_bfloat16 g_W_lo[Kk*Ff];
__device__ int   g_kidx[Bb*Nn];
__device__ int   g_perm[Bb*Nn];
__device__ float g_Ej [Bb*Nn];
__device__ float g_Fj [Bb*Nn];
__device__ float g_PzE[Bb*Nn];
__device__ float g_PzF[Bb*Nn];
__device__ float g_PE [Bb*Nn*Ff];
__device__ float g_PF [Bb*Nn*Ff];
__device__ float g_chE[Bb*Ff*NCH];
__device__ float g_chF[Bb*Ff*NCH];
__device__ float g_chzE[Bb*NCH];
__device__ float g_chzF[Bb*NCH];
__device__ float g_offE[Bb*NCH*Ff];
__device__ float g_offF[Bb*NCH*Ff];
__device__ float g_offzE[Bb*NCH];
__device__ float g_offzF[Bb*NCH];
__device__ float g_TF [Bb*Ff];
__device__ float g_TzF[Bb];
__device__ unsigned long long g_tick;   // monotonic ticket counter (replay-safe)

// ================= helpers =================
__device__ __forceinline__ uint32_t smem_u32(const void* p){
    uint32_t a;
    asm("{ .reg .u64 t; cvta.to.shared.u64 t, %1; cvt.u32.u64 %0, t; }" : "=r"(a) : "l"(p));
    return a;
}
__device__ __forceinline__ void ldsm_x4(uint32_t* r, uint32_t addr){
    asm volatile("ldmatrix.sync.aligned.m8n8.x4.shared.b16 {%0,%1,%2,%3}, [%4];"
        : "=r"(r[0]),"=r"(r[1]),"=r"(r[2]),"=r"(r[3]) : "r"(addr));
}
__device__ __forceinline__ void ldsm_x4t(uint32_t* r, uint32_t addr){
    asm volatile("ldmatrix.sync.aligned.m8n8.x4.trans.shared.b16 {%0,%1,%2,%3}, [%4];"
        : "=r"(r[0]),"=r"(r[1]),"=r"(r[2]),"=r"(r[3]) : "r"(addr));
}
__device__ __forceinline__ void mma16816(float* d, const uint32_t* a, const uint32_t* b){
    asm volatile("mma.sync.aligned.m16n8k16.row.col.f32.bf16.bf16.f32 "
        "{%0,%1,%2,%3}, {%4,%5,%6,%7}, {%8,%9}, {%0,%1,%2,%3};"
        : "+f"(d[0]),"+f"(d[1]),"+f"(d[2]),"+f"(d[3])
        : "r"(a[0]),"r"(a[1]),"r"(a[2]),"r"(a[3]), "r"(b[0]),"r"(b[1]));
}
__device__ __forceinline__ void cp16(uint32_t dst, const void* src){
    asm volatile("cp.async.cg.shared.global [%0], [%1], 16;" :: "r"(dst), "l"(src));
}
#define CP_COMMIT() asm volatile("cp.async.commit_group;" ::: "memory")
#define CP_WAIT(n)  asm volatile("cp.async.wait_group %0;" :: "n"(n) : "memory")

__device__ __forceinline__ void split_bf16(float x, __nv_bfloat16& hi, __nv_bfloat16& lo){
    hi = __float2bfloat16(x);
    lo = __float2bfloat16(x - __bfloat162float(hi));
}

// replay-safe grid barrier: monotonic ticket bands of GRID
__device__ __forceinline__ void gbar(){
    __syncthreads();
    if (threadIdx.x == 0){
        __threadfence();
        unsigned long long t = atomicAdd(&g_tick, 1ULL);
        unsigned long long target = (t/GRID + 1ULL)*GRID;
        volatile unsigned long long* p = &g_tick;
        while (*p < target) { }
        __threadfence();
    }
    __syncthreads();
}

// smem layout (bytes), double-buffered gemm staging
#define AP 72
#define BP 136
#define OFF_AHI 0
#define OFF_ALO 18432
#define OFF_BHI 36864
#define OFF_BLO 54272
#define PING_SZ 71680
#define SM_TOTAL (2*PING_SZ)

__device__ __forceinline__ void stage_cp(uint32_t sb, const __nv_bfloat16* hHiB,
                                         const __nv_bfloat16* hLoB,
                                         int kc, int p, int tid){
    uint32_t base = sb + p*PING_SZ;
    #pragma unroll
    for (int i=0;i<4;i++){
        int idx = tid + i*256;
        int r = idx >> 3, k16 = idx & 7;
        uint32_t dst = base + OFF_AHI + (uint32_t)(r*AP*2 + k16*16);
        cp16(dst, hHiB + (size_t)r*Kk + kc + k16*8);
        cp16(dst + (OFF_ALO-OFF_AHI), hLoB + (size_t)r*Kk + kc + k16*8);
    }
    #pragma unroll
    for (int i=0;i<4;i++){
        int idx = tid + i*256;
        int k = idx >> 4, n16 = idx & 15;
        uint32_t dst = base + OFF_BHI + (uint32_t)(k*BP*2 + n16*16);
        cp16(dst, g_W_hi + (size_t)(kc+k)*Ff + n16*8);
        cp16(dst + (OFF_BLO-OFF_BHI), g_W_lo + (size_t)(kc+k)*Ff + n16*8);
    }
}

// =================== THE persistent mega-kernel ===================
__global__ __launch_bounds__(NTHR, 1)
void mega(const float* __restrict__ h, const float* __restrict__ W,
          const float* __restrict__ ai, const float* __restrict__ aj,
          float* __restrict__ out)
{
    extern __shared__ char smem[];
    const int tid  = threadIdx.x;
    const int wid  = tid >> 5, lane = tid & 31;
    const int cta  = blockIdx.x;
    const int gw   = cta*8 + wid;            // global warp id 0..1023

    // ======== Phase 1: wa = W@a  + convert W to split bf16 ========
    {
        int t = cta*NTHR + tid;              // 0..32767
        if (t < (Kk*Ff)/4){
            float4 x = *(const float4*)&W[(size_t)t*4];
            __nv_bfloat16 h0,l0,h1,l1,h2,l2,h3,l3;
            split_bf16(x.x,h0,l0); split_bf16(x.y,h1,l1);
            split_bf16(x.z,h2,l2); split_bf16(x.w,h3,l3);
            __nv_bfloat162* ph = (__nv_bfloat162*)&g_W_hi[(size_t)t*4];
            __nv_bfloat162* pl = (__nv_bfloat162*)&g_W_lo[(size_t)t*4];
            ph[0] = {h0,h1}; ph[1] = {h2,h3};
            pl[0] = {l0,l1}; pl[1] = {l2,l3};
        }
        if (gw < Kk){
            const float* wr = &W[(size_t)gw*Ff];
            float pu=0.f, pv=0.f;
            #pragma unroll
            for (int q=0;q<4;q++){
                int n = lane + q*32;
                float w = wr[n];
                pu = fmaf(w, ai[n], pu);
                pv = fmaf(w, aj[n], pv);
            }
            #pragma unroll
            for (int s=16;s>0;s>>=1){
                pu += __shfl_xor_sync(0xffffffffu, pu, s);
                pv += __shfl_xor_sync(0xffffffffu, pv, s);
            }
            if (lane==0){ g_wa_i[gw]=pu; g_wa_j[gw]=pv; }
        }
    }
    gbar();

    // ======== Phase 2: u,v = h@wa + convert h to split bf16 ========
    for (int r16=0; r16<16; r16++){
        int row = gw*16 + r16;
        const float4* hr = (const float4*)&h[(size_t)row*Kk];
        float pu=0.f, pv=0.f;
        #pragma unroll
        for (int q=0;q<2;q++){
            int i4 = lane + q*32;
            float4 x = hr[i4];
            const float* wi = &g_wa_i[i4*4];
            const float* wj = &g_wa_j[i4*4];
            pu = fmaf(x.x,wi[0],fmaf(x.y,wi[1],fmaf(x.z,wi[2],fmaf(x.w,wi[3],pu))));
            pv = fmaf(x.x,wj[0],fmaf(x.y,wj[1],fmaf(x.z,wj[2],fmaf(x.w,wj[3],pv))));
            __nv_bfloat16 h0,l0,h1,l1,h2,l2,h3,l3;
            split_bf16(x.x,h0,l0); split_bf16(x.y,h1,l1);
            split_bf16(x.z,h2,l2); split_bf16(x.w,h3,l3);
            __nv_bfloat162* ph = (__nv_bfloat162*)&g_h_hi[(size_t)row*Kk + i4*4];
            __nv_bfloat162* pl = (__nv_bfloat162*)&g_h_lo[(size_t)row*Kk + i4*4];
            ph[0] = {h0,h1}; ph[1] = {h2,h3};
            pl[0] = {l0,l1}; pl[1] = {l2,l3};
        }
        #pragma unroll
        for (int s=16;s>0;s>>=1){
            pu += __shfl_xor_sync(0xffffffffu, pu, s);
            pv += __shfl_xor_sync(0xffffffffu, pv, s);
        }
        if (lane==0){ g_u[row]=pu; g_v[row]=pv; }
    }
    gbar();

    // ======== Phase 3a: gemm Wh = h@W (split-bf16 mma.sync + cp.async) ========
    {
        uint32_t sb = smem_u32(smem);
        int warp_m = wid & 1, warp_n = wid >> 1;
        int b = cta >> 4;
        int row0 = (cta & 15) * 128;
        const __nv_bfloat16* hHiB = g_h_hi + ((size_t)b*Nn + row0) * Kk;
        const __nv_bfloat16* hLoB = g_h_lo + ((size_t)b*Nn + row0) * Kk;

        float acc[4][4][4];
        #pragma unroll
        for (int mt=0;mt<4;mt++)
            #pragma unroll
            for (int nt=0;nt<4;nt++)
                #pragma unroll
                for (int q=0;q<4;q++) acc[mt][nt][q]=0.f;

        int within = lane & 7, blk = lane >> 3;
        uint32_t aRel = (uint32_t)(((warp_m*64 + within + (blk&1)*8) * AP + (blk>>1)*8) * 2);
        uint32_t bRel = (uint32_t)(((within + (blk&1)*8) * BP + warp_n*32 + (blk>>1)*8) * 2);

        stage_cp(sb, hHiB, hLoB, 0, 0, tid);
        CP_COMMIT();

        for (int c = 0; c < 4; c++){
            if (c < 3){
                stage_cp(sb, hHiB, hLoB, (c+1)*64, (c+1)&1, tid);
                CP_COMMIT();
                CP_WAIT(1);
            } else {
                CP_WAIT(0);
            }
            __syncthreads();

            uint32_t pb = sb + (c&1)*PING_SZ;
            uint32_t aBase = pb + OFF_AHI + aRel;
            uint32_t bBase = pb + OFF_BHI + bRel;
            #pragma unroll
            for (int ks = 0; ks < 4; ks++){
                uint32_t ah[4][4], al[4][4];
                #pragma unroll
                for (int mt=0;mt<4;mt++){
                    uint32_t ad = aBase + (uint32_t)(mt*16*AP*2 + ks*32);
                    ldsm_x4 (ah[mt], ad);
                    ldsm_x4 (al[mt], ad + (OFF_ALO-OFF_AHI));
                }
                uint32_t bh[2][4], bl[2][4];
                #pragma unroll
                for (int np=0;np<2;np++){
                    uint32_t bd = bBase + (uint32_t)(np*32 + ks*16*BP*2);
                    ldsm_x4t(bh[np], bd);
                    ldsm_x4t(bl[np], bd + (OFF_BLO-OFF_BHI));
                }
                #pragma unroll
                for (int mt=0;mt<4;mt++){
                    #pragma unroll
                    for (int nt=0;nt<4;nt++){
                        const uint32_t* pbh = &bh[nt>>1][(nt&1)*2];
                        const uint32_t* pbl = &bl[nt>>1][(nt&1)*2];
                        mma16816(acc[mt][nt], ah[mt], pbh);
                        mma16816(acc[mt][nt], ah[mt], pbl);
                        mma16816(acc[mt][nt], al[mt], pbh);
                    }
                }
            }
            __syncthreads();
        }

        int g = lane >> 2, tig = lane & 3;
        #pragma unroll
        for (int mt=0;mt<4;mt++){
            int r0a = row0 + warp_m*64 + mt*16 + g;
            #pragma unroll
            for (int nt=0;nt<4;nt++){
                int col = warp_n*32 + nt*8 + 2*tig;
                float2 d01; d01.x = acc[mt][nt][0]; d01.y = acc[mt][nt][1];
                float2 d23; d23.x = acc[mt][nt][2]; d23.y = acc[mt][nt][3];
                *(float2*)&g_Wh[((size_t)b*Nn + r0a    )*Ff + col] = d01;
                *(float2*)&g_Wh[((size_t)b*Nn + r0a + 8)*Ff + col] = d23;
            }
        }
    }
    __syncthreads();

    // ======== Phase 3b: rank + branch index (reuse smem as sv[2048]) ========
    {
        float* sv = (float*)smem;
        int br = cta >> 4;
        int rbase = (cta & 15) * 128;
        for (int e=tid; e<2048; e+=NTHR) sv[e] = g_v[br*Nn+e];
        __syncthreads();
        if (tid < 128){
            int i = rbase + tid;
            float vi  = sv[i];
            float nui = -g_u[br*Nn+i];
            int rnk=0, ck=0;
            const float4* sv4 = (const float4*)sv;
            #pragma unroll 4
            for (int q=0; q<512; q++){
                float4 x = sv4[q];
                int m0 = q*4;
                rnk += (x.x>vi) + (x.y>vi) + (x.z>vi) + (x.w>vi);
                ck  += (x.x>nui)+ (x.y>nui)+ (x.z>nui)+ (x.w>nui);
                rnk += ((x.x==vi)&&(m0  <i)) + ((x.y==vi)&&(m0+1<i))
                     + ((x.z==vi)&&(m0+2<i)) + ((x.w==vi)&&(m0+3<i));
            }
            g_kidx[br*Nn+i] = ck;
            g_perm[br*Nn+rnk] = i;
            g_Ej[br*Nn+rnk] = __expf(vi);
            g_Fj[br*Nn+rnk] = __expf(0.01f*vi);
        }
    }
    gbar();

    // ======== Phase 4: chunk-local prefixes (2 half-block tasks per CTA) ======
    {
        int hf  = tid >> 7;                  // 0/1
        int f   = tid & 127;
        int gid = cta*2 + hf;                // 0..255
        int b   = gid >> 5, ch = gid & 31;
        int base = ch*CSZ;
        char* hb = smem + hf*1024;
        int*   sperm = (int*)hb;
        float* sE    = (float*)(hb+256);
        float* sF    = (float*)(hb+512);
        if (f < CSZ){
            sperm[f]=g_perm[b*Nn+base+f];
            sE[f]=g_Ej[b*Nn+base+f];
            sF[f]=g_Fj[b*Nn+base+f];
        }
        __syncthreads();

        float wreg[CSZ];
        #pragma unroll
        for (int m=0;m<CSZ;m++)
            wreg[m] = g_Wh[((size_t)b*Nn + sperm[m])*Ff + f];

        if (f < 32){
            float e0=sE[f], e1=sE[f+32], f0=sF[f], f1=sF[f+32];
            float pe0=e0, pe1=e1, pf0=f0, pf1=f1;
            #pragma unroll
            for (int s=1;s<32;s<<=1){
                float a=__shfl_up_sync(0xffffffffu, pe0, s);
                float bq=__shfl_up_sync(0xffffffffu, pe1, s);
                float cq=__shfl_up_sync(0xffffffffu, pf0, s);
                float d=__shfl_up_sync(0xffffffffu, pf1, s);
                if (f>=s){ pe0+=a; pe1+=bq; pf0+=cq; pf1+=d; }
            }
            float te0=__shfl_sync(0xffffffffu, pe0, 31);
            float tf0=__shfl_sync(0xffffffffu, pf0, 31);
            pe1 += te0; pf1 += tf0;
            g_PzE[b*Nn+base+f]    = pe0;
            g_PzE[b*Nn+base+32+f] = pe1;
            g_PzF[b*Nn+base+f]    = pf0;
            g_PzF[b*Nn+base+32+f] = pf1;
            if (f==31){ g_chzE[b*NCH+ch]=pe1; g_chzF[b*NCH+ch]=pf1; }
        }

        float ae=0.f, af=0.f;
        #pragma unroll
        for (int m=0;m<CSZ;m++){
            ae = fmaf(sE[m], wreg[m], ae);
            af = fmaf(sF[m], wreg[m], af);
            size_t o = ((size_t)b*Nn + base + m)*Ff + f;
            g_PE[o]=ae; g_PF[o]=af;
        }
        g_chE[((size_t)b*Ff+f)*NCH+ch]=ae;
        g_chF[((size_t)b*Ff+f)*NCH+ch]=af;
    }
    gbar();

    // ======== Phase 5: scan of chunk totals (warp per (b,f)) ========
    {
        int b = gw >> 7, f = gw & 127;       // gw in 0..1023 exactly covers 8x128
        float ev = g_chE[((size_t)b*Ff+f)*NCH + lane];
        float fv = g_chF[((size_t)b*Ff+f)*NCH + lane];
        float ie = ev, iff = fv;
        #pragma unroll
        for (int s=1;s<32;s<<=1){
            float te = __shfl_up_sync(0xffffffffu, ie, s);
            float tf = __shfl_up_sync(0xffffffffu, iff, s);
            if (lane>=s){ ie+=te; iff+=tf; }
        }
        g_offE[((size_t)b*NCH+lane)*Ff+f] = ie - ev;
        g_offF[((size_t)b*NCH+lane)*Ff+f] = iff - fv;
        if (lane==31) g_TF[b*Ff+f] = iff;

        if (gw < 8){
            int bz = gw;
            float ze = g_chzE[bz*NCH+lane];
            float zf = g_chzF[bz*NCH+lane];
            float ize=ze, izf=zf;
            #pragma unroll
            for (int s=1;s<32;s<<=1){
                float a=__shfl_up_sync(0xffffffffu, ize, s);
                float c=__shfl_up_sync(0xffffffffu, izf, s);
                if (lane>=s){ ize+=a; izf+=c; }
            }
            g_offzE[bz*NCH+lane] = ize - ze;
            g_offzF[bz*NCH+lane] = izf - zf;
            if (lane==31) g_TzF[bz] = izf;
        }
    }
    gbar();

    // ======== Phase 6: finalize ========
    {
        int tx = tid & 127;
        #pragma unroll 4
        for (int it=0; it<64; it++){
            int rg  = cta*128 + it*2 + (tid>>7);   // global row 0..16383
            int b   = rg >> 11;
            int row = rg & 2047;

            int k = g_kidx[b*Nn+row];
            float uu = g_u[b*Nn+row];
            float Ei = __expf(uu), Fi = __expf(0.01f*uu);
            float TFf = g_TF[b*Ff+tx];
            float TzF = g_TzF[b];

            float pe=0.f, pf=0.f, pze=0.f, pzf=0.f;
            if (k>0){
                int km = k-1, c = km>>6;
                size_t o = ((size_t)b*Nn+km)*Ff+tx;
                pe  = g_PE[o] + g_offE[(b*NCH+c)*Ff+tx];
                pf  = g_PF[o] + g_offF[(b*NCH+c)*Ff+tx];
                pze = g_PzE[b*Nn+km] + g_offzE[b*NCH+c];
                pzf = g_PzF[b*Nn+km] + g_offzF[b*NCH+c];
            }
            float num = Ei*pe + Fi*(TFf - pf);
            float den = Ei*pze + Fi*(TzF - pzf);
            out[((size_t)b*Nn+row)*Ff+tx] = num/den;
        }
    }
}

// ================= launch =================
extern "C" void kernel_launch(void* const* d_in, const int* in_sizes, int n_in,
                              void* d_out, int out_size) {
    const float* h  = (const float*)d_in[0];
    const float* W  = (const float*)d_in[1];
    const float* ai = (const float*)d_in[2];
    const float* aj = (const float*)d_in[3];
    float* out = (float*)d_out;

    cudaFuncSetAttribute(mega, cudaFuncAttributeMaxDynamicSharedMemorySize, SM_TOTAL);
    mega<<<GRID, NTHR, SM_TOTAL>>>(h, W, ai, aj, out);
}

// round 17
// speedup vs baseline: 1.1848x; 1.1848x over previous
#include <cuda_runtime.h>
#include <cuda_bf16.h>
#include <cstdint>

#define Bb 8
#define Nn 2048
#define Kk 256
#define Ff 128
#define NCH 64
#define CSZ 32
#define GRID 128
#define NTHR 512

// -------- scratch (device globals) --------
__device__ __align__(16) float g_Wh[Bb*Nn*Ff];
__device__ float g_u [Bb*Nn];
__device__ float g_v [Bb*Nn];
__device__ float g_wa_i[Kk];
__device__ float g_wa_j[Kk];
__device__ __align__(16) __nv_bfloat16 g_h_hi[Bb*Nn*Kk];
__device__ __align__(16) __nv_bfloat16 g_h_lo[Bb*Nn*Kk];
__device__ __align__(16) __nv_bfloat16 g_W_hi[Kk*Ff];
__device__ __align__(16) __nv_bfloat16 g_W_lo[Kk*Ff];
__device__ int   g_kidx[Bb*Nn];
__device__ int   g_perm[Bb*Nn];
__device__ float g_Ej [Bb*Nn];
__device__ float g_Fj [Bb*Nn];
__device__ float g_PzE[Bb*Nn];
__device__ float g_PzF[Bb*Nn];
__device__ float g_PE [Bb*Nn*Ff];
__device__ float g_PF [Bb*Nn*Ff];
__device__ float g_chE[Bb*Ff*NCH];
__device__ float g_chF[Bb*Ff*NCH];
__device__ float g_chzE[Bb*NCH];
__device__ float g_chzF[Bb*NCH];
__device__ float g_offE[Bb*NCH*Ff];
__device__ float g_offF[Bb*NCH*Ff];
__device__ float g_offzE[Bb*NCH];
__device__ float g_offzF[Bb*NCH];
__device__ float g_TF [Bb*Ff];
__device__ float g_TzF[Bb];
__device__ unsigned long long g_tick;   // monotonic ticket counter (replay-safe)

// ================= helpers =================
__device__ __forceinline__ uint32_t smem_u32(const void* p){
    uint32_t a;
    asm("{ .reg .u64 t; cvta.to.shared.u64 t, %1; cvt.u32.u64 %0, t; }" : "=r"(a) : "l"(p));
    return a;
}
__device__ __forceinline__ void ldsm_x4(uint32_t* r, uint32_t addr){
    asm volatile("ldmatrix.sync.aligned.m8n8.x4.shared.b16 {%0,%1,%2,%3}, [%4];"
        : "=r"(r[0]),"=r"(r[1]),"=r"(r[2]),"=r"(r[3]) : "r"(addr));
}
__device__ __forceinline__ void ldsm_x4t(uint32_t* r, uint32_t addr){
    asm volatile("ldmatrix.sync.aligned.m8n8.x4.trans.shared.b16 {%0,%1,%2,%3}, [%4];"
        : "=r"(r[0]),"=r"(r[1]),"=r"(r[2]),"=r"(r[3]) : "r"(addr));
}
__device__ __forceinline__ void mma16816(float* d, const uint32_t* a, const uint32_t* b){
    asm volatile("mma.sync.aligned.m16n8k16.row.col.f32.bf16.bf16.f32 "
        "{%0,%1,%2,%3}, {%4,%5,%6,%7}, {%8,%9}, {%0,%1,%2,%3};"
        : "+f"(d[0]),"+f"(d[1]),"+f"(d[2]),"+f"(d[3])
        : "r"(a[0]),"r"(a[1]),"r"(a[2]),"r"(a[3]), "r"(b[0]),"r"(b[1]));
}
__device__ __forceinline__ void cp16(uint32_t dst, const void* src){
    asm volatile("cp.async.cg.shared.global [%0], [%1], 16;" :: "r"(dst), "l"(src));
}
#define CP_COMMIT() asm volatile("cp.async.commit_group;" ::: "memory")
#define CP_WAIT(n)  asm volatile("cp.async.wait_group %0;" :: "n"(n) : "memory")

__device__ __forceinline__ void split_bf16(float x, __nv_bfloat16& hi, __nv_bfloat16& lo){
    hi = __float2bfloat16(x);
    lo = __float2bfloat16(x - __bfloat162float(hi));
}

// replay-safe grid barrier: monotonic ticket bands of GRID
__device__ __forceinline__ void gbar(){
    __syncthreads();
    if (threadIdx.x == 0){
        __threadfence();
        unsigned long long t = atomicAdd(&g_tick, 1ULL);
        unsigned long long target = (t/GRID + 1ULL)*GRID;
        volatile unsigned long long* p = &g_tick;
        while (*p < target) { }
        __threadfence();
    }
    __syncthreads();
}

// smem layout (bytes), double-buffered gemm staging
#define AP 72
#define BP 136
#define OFF_AHI 0
#define OFF_ALO 18432
#define OFF_BHI 36864
#define OFF_BLO 54272
#define PING_SZ 71680
#define SM_TOTAL (2*PING_SZ)

__device__ __forceinline__ void stage_cp(uint32_t sb, const __nv_bfloat16* hHiB,
                                         const __nv_bfloat16* hLoB,
                                         int kc, int p, int tid){
    uint32_t base = sb + p*PING_SZ;
    #pragma unroll
    for (int i=0;i<2;i++){
        int idx = tid + i*NTHR;          // 0..1023
        int r = idx >> 3, k16 = idx & 7;
        uint32_t dst = base + OFF_AHI + (uint32_t)(r*AP*2 + k16*16);
        cp16(dst, hHiB + (size_t)r*Kk + kc + k16*8);
        cp16(dst + (OFF_ALO-OFF_AHI), hLoB + (size_t)r*Kk + kc + k16*8);
    }
    #pragma unroll
    for (int i=0;i<2;i++){
        int idx = tid + i*NTHR;
        int k = idx >> 4, n16 = idx & 15;
        uint32_t dst = base + OFF_BHI + (uint32_t)(k*BP*2 + n16*16);
        cp16(dst, g_W_hi + (size_t)(kc+k)*Ff + n16*8);
        cp16(dst + (OFF_BLO-OFF_BHI), g_W_lo + (size_t)(kc+k)*Ff + n16*8);
    }
}

// =================== THE persistent mega-kernel (512 thr) ===================
__global__ __launch_bounds__(NTHR, 1)
void mega(const float* __restrict__ h, const float* __restrict__ W,
          const float* __restrict__ ai, const float* __restrict__ aj,
          float* __restrict__ out)
{
    extern __shared__ char smem[];
    const int tid  = threadIdx.x;
    const int wid  = tid >> 5, lane = tid & 31;
    const int cta  = blockIdx.x;
    const int gw   = cta*16 + wid;           // global warp id 0..2047

    // ======== Phase 1: wa = W@a + convert W ========
    {
        int t = cta*NTHR + tid;              // 0..65535
        if (t < (Kk*Ff)/4){
            float4 x = *(const float4*)&W[(size_t)t*4];
            __nv_bfloat16 h0,l0,h1,l1,h2,l2,h3,l3;
            split_bf16(x.x,h0,l0); split_bf16(x.y,h1,l1);
            split_bf16(x.z,h2,l2); split_bf16(x.w,h3,l3);
            __nv_bfloat162* ph = (__nv_bfloat162*)&g_W_hi[(size_t)t*4];
            __nv_bfloat162* pl = (__nv_bfloat162*)&g_W_lo[(size_t)t*4];
            ph[0] = {h0,h1}; ph[1] = {h2,h3};
            pl[0] = {l0,l1}; pl[1] = {l2,l3};
        }
        if (gw < Kk){
            const float* wr = &W[(size_t)gw*Ff];
            float pu=0.f, pv=0.f;
            #pragma unroll
            for (int q=0;q<4;q++){
                int n = lane + q*32;
                float w = wr[n];
                pu = fmaf(w, ai[n], pu);
                pv = fmaf(w, aj[n], pv);
            }
            #pragma unroll
            for (int s=16;s>0;s>>=1){
                pu += __shfl_xor_sync(0xffffffffu, pu, s);
                pv += __shfl_xor_sync(0xffffffffu, pv, s);
            }
            if (lane==0){ g_wa_i[gw]=pu; g_wa_j[gw]=pv; }
        }
    }
    gbar();

    // ======== Phase 2: u,v = h@wa + convert h ========
    #pragma unroll 2
    for (int r8=0; r8<8; r8++){
        int row = gw*8 + r8;
        const float4* hr = (const float4*)&h[(size_t)row*Kk];
        float pu=0.f, pv=0.f;
        #pragma unroll
        for (int q=0;q<2;q++){
            int i4 = lane + q*32;
            float4 x = hr[i4];
            const float* wi = &g_wa_i[i4*4];
            const float* wj = &g_wa_j[i4*4];
            pu = fmaf(x.x,wi[0],fmaf(x.y,wi[1],fmaf(x.z,wi[2],fmaf(x.w,wi[3],pu))));
            pv = fmaf(x.x,wj[0],fmaf(x.y,wj[1],fmaf(x.z,wj[2],fmaf(x.w,wj[3],pv))));
            __nv_bfloat16 h0,l0,h1,l1,h2,l2,h3,l3;
            split_bf16(x.x,h0,l0); split_bf16(x.y,h1,l1);
            split_bf16(x.z,h2,l2); split_bf16(x.w,h3,l3);
            __nv_bfloat162* ph = (__nv_bfloat162*)&g_h_hi[(size_t)row*Kk + i4*4];
            __nv_bfloat162* pl = (__nv_bfloat162*)&g_h_lo[(size_t)row*Kk + i4*4];
            ph[0] = {h0,h1}; ph[1] = {h2,h3};
            pl[0] = {l0,l1}; pl[1] = {l2,l3};
        }
        #pragma unroll
        for (int s=16;s>0;s>>=1){
            pu += __shfl_xor_sync(0xffffffffu, pu, s);
            pv += __shfl_xor_sync(0xffffffffu, pv, s);
        }
        if (lane==0){ g_u[row]=pu; g_v[row]=pv; }
    }
    gbar();

    // ======== Phase 3a: gemm Wh = h@W (16 warps: 32x32 per warp) ========
    {
        uint32_t sb = smem_u32(smem);
        int warp_m = wid & 3, warp_n = wid >> 2;
        int b = cta >> 4;
        int row0 = (cta & 15) * 128;
        const __nv_bfloat16* hHiB = g_h_hi + ((size_t)b*Nn + row0) * Kk;
        const __nv_bfloat16* hLoB = g_h_lo + ((size_t)b*Nn + row0) * Kk;

        float acc[2][4][4];
        #pragma unroll
        for (int mt=0;mt<2;mt++)
            #pragma unroll
            for (int nt=0;nt<4;nt++)
                #pragma unroll
                for (int q=0;q<4;q++) acc[mt][nt][q]=0.f;

        int within = lane & 7, blk = lane >> 3;
        uint32_t aRel = (uint32_t)(((warp_m*32 + within + (blk&1)*8) * AP + (blk>>1)*8) * 2);
        uint32_t bRel = (uint32_t)(((within + (blk&1)*8) * BP + warp_n*32 + (blk>>1)*8) * 2);

        stage_cp(sb, hHiB, hLoB, 0, 0, tid);
        CP_COMMIT();

        for (int c = 0; c < 4; c++){
            if (c < 3){
                stage_cp(sb, hHiB, hLoB, (c+1)*64, (c+1)&1, tid);
                CP_COMMIT();
                CP_WAIT(1);
            } else {
                CP_WAIT(0);
            }
            __syncthreads();

            uint32_t pb = sb + (c&1)*PING_SZ;
            uint32_t aBase = pb + OFF_AHI + aRel;
            uint32_t bBase = pb + OFF_BHI + bRel;
            #pragma unroll
            for (int ks = 0; ks < 4; ks++){
                uint32_t ah[2][4], al[2][4];
                #pragma unroll
                for (int mt=0;mt<2;mt++){
                    uint32_t ad = aBase + (uint32_t)(mt*16*AP*2 + ks*32);
                    ldsm_x4 (ah[mt], ad);
                    ldsm_x4 (al[mt], ad + (OFF_ALO-OFF_AHI));
                }
                uint32_t bh[2][4], bl[2][4];
                #pragma unroll
                for (int np=0;np<2;np++){
                    uint32_t bd = bBase + (uint32_t)(np*32 + ks*16*BP*2);
                    ldsm_x4t(bh[np], bd);
                    ldsm_x4t(bl[np], bd + (OFF_BLO-OFF_BHI));
                }
                #pragma unroll
                for (int mt=0;mt<2;mt++){
                    #pragma unroll
                    for (int nt=0;nt<4;nt++){
                        const uint32_t* pbh = &bh[nt>>1][(nt&1)*2];
                        const uint32_t* pbl = &bl[nt>>1][(nt&1)*2];
                        mma16816(acc[mt][nt], ah[mt], pbh);
                        mma16816(acc[mt][nt], ah[mt], pbl);
                        mma16816(acc[mt][nt], al[mt], pbh);
                    }
                }
            }
            __syncthreads();
        }

        int g = lane >> 2, tig = lane & 3;
        #pragma unroll
        for (int mt=0;mt<2;mt++){
            int r0a = row0 + warp_m*32 + mt*16 + g;
            #pragma unroll
            for (int nt=0;nt<4;nt++){
                int col = warp_n*32 + nt*8 + 2*tig;
                float2 d01; d01.x = acc[mt][nt][0]; d01.y = acc[mt][nt][1];
                float2 d23; d23.x = acc[mt][nt][2]; d23.y = acc[mt][nt][3];
                *(float2*)&g_Wh[((size_t)b*Nn + r0a    )*Ff + col] = d01;
                *(float2*)&g_Wh[((size_t)b*Nn + r0a + 8)*Ff + col] = d23;
            }
        }
    }
    __syncthreads();

    // ======== Phase 3b: rank (all 512 threads; quarter-scan + smem combine) ====
    {
        float* sv  = (float*)smem;               // 8 KB
        int* srnk  = (int*)(smem + 8192);        // 512 B
        int* sck   = (int*)(smem + 8704);        // 512 B
        int br = cta >> 4;
        int rbase = (cta & 15) * 128;
        for (int e=tid; e<2048; e+=NTHR) sv[e] = g_v[br*Nn+e];
        if (tid < 128){ srnk[tid]=0; sck[tid]=0; }
        __syncthreads();

        int rloc = tid & 127;
        int i = rbase + rloc;
        int qtr = tid >> 7;                       // 0..3
        float vi  = sv[i];
        float nui = -g_u[br*Nn+i];
        int rnk=0, ck=0;
        const float4* sv4 = (const float4*)sv;
        #pragma unroll 4
        for (int q=qtr*128; q<qtr*128+128; q++){
            float4 x = sv4[q];
            int m0 = q*4;
            rnk += (x.x>vi) + (x.y>vi) + (x.z>vi) + (x.w>vi);
            ck  += (x.x>nui)+ (x.y>nui)+ (x.z>nui)+ (x.w>nui);
            rnk += ((x.x==vi)&&(m0  <i)) + ((x.y==vi)&&(m0+1<i))
                 + ((x.z==vi)&&(m0+2<i)) + ((x.w==vi)&&(m0+3<i));
        }
        atomicAdd(&srnk[rloc], rnk);
        atomicAdd(&sck [rloc], ck);
        __syncthreads();
        if (tid < 128){
            int i2 = rbase + tid;
            float vi2 = sv[i2];
            int r2 = srnk[tid];
            g_kidx[br*Nn+i2] = sck[tid];
            g_perm[br*Nn+r2] = i2;
            g_Ej[br*Nn+r2] = __expf(vi2);
            g_Fj[br*Nn+r2] = __expf(0.01f*vi2);
        }
    }
    gbar();

    // ======== Phase 4: chunk-local prefixes (CSZ=32, 4 groups/CTA) ======
    {
        int grp = tid >> 7;                  // 0..3
        int f   = tid & 127;
        int gid = cta*4 + grp;               // 0..511 = b*NCH+ch
        int b   = gid >> 6, ch = gid & 63;
        int base = ch*CSZ;
        char* hb = smem + grp*512;
        int*   sperm = (int*)hb;
        float* sE    = (float*)(hb+128);
        float* sF    = (float*)(hb+256);
        if (f < CSZ){
            sperm[f]=g_perm[b*Nn+base+f];
            sE[f]=g_Ej[b*Nn+base+f];
            sF[f]=g_Fj[b*Nn+base+f];
        }
        __syncthreads();

        float wreg[CSZ];
        #pragma unroll
        for (int m=0;m<CSZ;m++)
            wreg[m] = g_Wh[((size_t)b*Nn + sperm[m])*Ff + f];

        if (f < 32){
            float pe0=sE[f], pf0=sF[f];
            float e0=pe0, f0=pf0;
            #pragma unroll
            for (int s=1;s<32;s<<=1){
                float a=__shfl_up_sync(0xffffffffu, pe0, s);
                float cq=__shfl_up_sync(0xffffffffu, pf0, s);
                if (f>=s){ pe0+=a; pf0+=cq; }
            }
            (void)e0; (void)f0;
            g_PzE[b*Nn+base+f] = pe0;
            g_PzF[b*Nn+base+f] = pf0;
            if (f==31){ g_chzE[b*NCH+ch]=pe0; g_chzF[b*NCH+ch]=pf0; }
        }

        float ae=0.f, af=0.f;
        #pragma unroll
        for (int m=0;m<CSZ;m++){
            ae = fmaf(sE[m], wreg[m], ae);
            af = fmaf(sF[m], wreg[m], af);
            size_t o = ((size_t)b*Nn + base + m)*Ff + f;
            g_PE[o]=ae; g_PF[o]=af;
        }
        g_chE[((size_t)b*Ff+f)*NCH+ch]=ae;
        g_chF[((size_t)b*Ff+f)*NCH+ch]=af;
    }
    gbar();

    // ======== Phase 5: scan of 64 chunk totals (warp per (b,f)) ========
    {
        if (gw < 1024){
            int b = gw >> 7, f = gw & 127;
            const float* pE = &g_chE[((size_t)b*Ff+f)*NCH];
            const float* pF = &g_chF[((size_t)b*Ff+f)*NCH];
            float e0 = pE[lane], e1 = pE[lane+32];
            float f0 = pF[lane], f1 = pF[lane+32];
            float pe0=e0, pe1=e1, pf0=f0, pf1=f1;
            #pragma unroll
            for (int s=1;s<32;s<<=1){
                float a=__shfl_up_sync(0xffffffffu, pe0, s);
                float bq=__shfl_up_sync(0xffffffffu, pe1, s);
                float cq=__shfl_up_sync(0xffffffffu, pf0, s);
                float d=__shfl_up_sync(0xffffffffu, pf1, s);
                if (lane>=s){ pe0+=a; pe1+=bq; pf0+=cq; pf1+=d; }
            }
            float te0=__shfl_sync(0xffffffffu, pe0, 31);
            float tf0=__shfl_sync(0xffffffffu, pf0, 31);
            pe1 += te0; pf1 += tf0;
            g_offE[((size_t)b*NCH+lane   )*Ff+f] = pe0 - e0;
            g_offE[((size_t)b*NCH+lane+32)*Ff+f] = pe1 - e1;
            g_offF[((size_t)b*NCH+lane   )*Ff+f] = pf0 - f0;
            g_offF[((size_t)b*NCH+lane+32)*Ff+f] = pf1 - f1;
            if (lane==31) g_TF[b*Ff+f] = pf1;
        }
        if (gw < 8){
            int bz = gw;
            float e0 = g_chzE[bz*NCH+lane], e1 = g_chzE[bz*NCH+lane+32];
            float f0 = g_chzF[bz*NCH+lane], f1 = g_chzF[bz*NCH+lane+32];
            float pe0=e0, pe1=e1, pf0=f0, pf1=f1;
            #pragma unroll
            for (int s=1;s<32;s<<=1){
                float a=__shfl_up_sync(0xffffffffu, pe0, s);
                float bq=__shfl_up_sync(0xffffffffu, pe1, s);
                float cq=__shfl_up_sync(0xffffffffu, pf0, s);
                float d=__shfl_up_sync(0xffffffffu, pf1, s);
                if (lane>=s){ pe0+=a; pe1+=bq; pf0+=cq; pf1+=d; }
            }
            float te0=__shfl_sync(0xffffffffu, pe0, 31);
            float tf0=__shfl_sync(0xffffffffu, pf0, 31);
            pe1 += te0; pf1 += tf0;
            g_offzE[bz*NCH+lane   ] = pe0 - e0;
            g_offzE[bz*NCH+lane+32] = pe1 - e1;
            g_offzF[bz*NCH+lane   ] = pf0 - f0;
            g_offzF[bz*NCH+lane+32] = pf1 - f1;
            if (lane==31) g_TzF[bz] = pf1;
        }
    }
    gbar();

    // ======== Phase 6: finalize ========
    {
        int tx = tid & 127;
        #pragma unroll 4
        for (int it=0; it<32; it++){
            int rg  = cta*128 + it*4 + (tid>>7);   // global row 0..16383
            int b   = rg >> 11;
            int row = rg & 2047;

            int k = g_kidx[b*Nn+row];
            float uu = g_u[b*Nn+row];
            float Ei = __expf(uu), Fi = __expf(0.01f*uu);
            float TFf = g_TF[b*Ff+tx];
            float TzF = g_TzF[b];

            float pe=0.f, pf=0.f, pze=0.f, pzf=0.f;
            if (k>0){
                int km = k-1, c = km>>5;
                size_t o = ((size_t)b*Nn+km)*Ff+tx;
                pe  = g_PE[o] + g_offE[(b*NCH+c)*Ff+tx];
                pf  = g_PF[o] + g_offF[(b*NCH+c)*Ff+tx];
                pze = g_PzE[b*Nn+km] + g_offzE[b*NCH+c];
                pzf = g_PzF[b*Nn+km] + g_offzF[b*NCH+c];
            }
            float num = Ei*pe + Fi*(TFf - pf);
            float den = Ei*pze + Fi*(TzF - pzf);
            out[((size_t)b*Nn+row)*Ff+tx] = num/den;
        }
    }
}

// ================= launch =================
extern "C" void kernel_launch(void* const* d_in, const int* in_sizes, int n_in,
                              void* d_out, int out_size) {
    const float* h  = (const float*)d_in[0];
    const float* W  = (const float*)d_in[1];
    const float* ai = (const float*)d_in[2];
    const float* aj = (const float*)d_in[3];
    float* out = (float*)d_out;

    cudaFuncSetAttribute(mega, cudaFuncAttributeMaxDynamicSharedMemorySize, SM_TOTAL);
    mega<<<GRID, NTHR, SM_TOTAL>>>(h, W, ai, aj, out);
}